// round 9
// baseline (speedup 1.0000x reference)
#include <cuda_runtime.h>

// ReduceBoundingBoxes, SINGLE kernel, SINGLE block.
// Bucketed counting "sort" with single-occupancy fast path:
//   A: zero out + zero hist + L2-prefetch ch1..4 + histogram ch0
//   C: block prefix-sum over 4096 buckets
//   D: bucket count==1 -> rank known -> gather+write row immediately;
//      collisions -> scat + cidx list
//   E: resolve collision ranks (expected ~100 elems), gather+write
//   F: warp-0 greedy NMS over non-degenerate boxes (flags from bx)
// x: (5, 80, 80) f32 channel-major. out: (6400, 5) f32.
//
// key = (u64(~bits(score)) << 32) | idx ; ascending == (score desc, idx asc).
// Valid scores s in (0.9, 1.0) share exponent 126 -> u = ~bits(s) lies in
// (0xC0800000, 0xC099999A); bucket = clamp((u - 0xC0800000) >> 9, 0, 4095)
// is monotone in u. Out-of-range scores clamp into end buckets, resolved by
// exact u64 compares -> correct for any input.

#define NPIX 6400
#define NT   1024
#define NB   4096

// dynamic smem layout (bytes):
//   [0,     16384)  int cursor[4096]   (hist -> running offsets)
//                   reused as u8 kb[6400] after D/E
//   [16384, 32776)  int base0[4097] (+pad)
//   [32776, 83976)  u64 scat[6400]     (collision keys, bucket-ordered)
//                   reused as int ndlist[6400] after E
//   [83976, 96784)  u16 cidx[6400] (+pad) (collision slot list)
//   [96784, 199184) float4 bx[6400]    (boxes by rank, for NMS)
#define CUR_OFF    0
#define BASE_OFF   16384
#define SCAT_OFF   32776
#define CIDX_OFF   83976
#define BX_OFF     96784
#define SMEM_BYTES 199184

__device__ __forceinline__ int bucket_of(unsigned u) {
    unsigned d = u - 0xC0800000u;
    int b = (u < 0xC0800000u) ? 0 : (int)(d >> 9);
    return b > (NB - 1) ? (NB - 1) : b;
}

__global__ void __launch_bounds__(NT, 1)
bb_kernel(const float* __restrict__ x, float* __restrict__ out) {
    extern __shared__ unsigned char smem[];
    int*                cursor = (int*)(smem + CUR_OFF);
    unsigned char*      kb     = smem + CUR_OFF;          // reuse after D/E
    int*                base0  = (int*)(smem + BASE_OFF);
    unsigned long long* scat   = (unsigned long long*)(smem + SCAT_OFF);
    int*                ndlist = (int*)(smem + SCAT_OFF); // reuse after E
    unsigned short*     cidx   = (unsigned short*)(smem + CIDX_OFF);
    float4*             bx     = (float4*)(smem + BX_OFF);
    __shared__ int wsum[32];
    __shared__ int sM;
    __shared__ int sC;

    const int tid  = threadIdx.x;
    const int lane = tid & 31;
    const int wid  = tid >> 5;

    // ---- A: zero out + zero hist + prefetch ch1..4 + histogram ch0 ----
    float4* o4 = (float4*)out;
    #pragma unroll
    for (int i = tid; i < (NPIX * 5) / 4; i += NT)
        o4[i] = make_float4(0.f, 0.f, 0.f, 0.f);
    #pragma unroll
    for (int i = tid; i < NB; i += NT) cursor[i] = 0;
    if (tid < 800) {   // 102400 B / 128 B lines
        const char* p = (const char*)(x + NPIX) + tid * 128;
        asm volatile("prefetch.global.L2 [%0];" :: "l"(p));
    }
    if (tid == 0) sC = 0;
    __syncthreads();
    #pragma unroll
    for (int i = tid; i < NPIX; i += NT) {
        float s = x[i];                      // channel 0 (prob)
        if (s > 0.9f)
            atomicAdd(&cursor[bucket_of(~__float_as_uint(s))], 1);
    }
    __syncthreads();

    // ---- C: exclusive prefix sum over 4096 buckets (4 per thread) ----
    const int t4 = tid * 4;
    int c0 = cursor[t4], c1 = cursor[t4 + 1];
    int c2 = cursor[t4 + 2], c3 = cursor[t4 + 3];
    int local = c0 + c1 + c2 + c3;
    int v = local;
    #pragma unroll
    for (int j = 1; j < 32; j <<= 1) {
        int n = __shfl_up_sync(0xffffffffu, v, j);
        if (lane >= j) v += n;
    }
    if (lane == 31) wsum[wid] = v;
    __syncthreads();
    if (wid == 0) {
        int w = wsum[lane];
        #pragma unroll
        for (int j = 1; j < 32; j <<= 1) {
            int n = __shfl_up_sync(0xffffffffu, w, j);
            if (lane >= j) w += n;
        }
        wsum[lane] = w;
        if (lane == 31) sM = w;              // total valid count
    }
    __syncthreads();
    int ex = v - local + (wid ? wsum[wid - 1] : 0);
    base0[t4]     = ex;
    base0[t4 + 1] = ex + c0;
    base0[t4 + 2] = ex + c0 + c1;
    base0[t4 + 3] = ex + c0 + c1 + c2;
    cursor[t4]     = ex;
    cursor[t4 + 1] = ex + c0;
    cursor[t4 + 2] = ex + c0 + c1;
    cursor[t4 + 3] = ex + c0 + c1 + c2;
    if (tid == 0) base0[NB] = sM;
    __syncthreads();
    const int M = sM;

    // ---- D: singles fast path (rank known) / collisions -> scat ----
    // b5 = (f0, f1, f0+f2, f1+f3, f4); box = (f1, f0+f2, f1+f3, f4)
    #pragma unroll
    for (int i = tid; i < NPIX; i += NT) {
        float s = x[i];                      // L1-hot reload
        if (s > 0.9f) {
            unsigned u = ~__float_as_uint(s);
            int b = bucket_of(u);
            int s0 = base0[b];
            if (base0[b + 1] - s0 == 1) {
                int r = s0;
                float f1 = x[NPIX + i];
                float f2 = x[2 * NPIX + i];
                float f3 = x[3 * NPIX + i];
                float f4 = x[4 * NPIX + i];
                float cc2 = s + f2;
                float cc3 = f1 + f3;
                out[r * 5 + 0] = s;
                out[r * 5 + 1] = f1;
                out[r * 5 + 2] = cc2;
                out[r * 5 + 3] = cc3;
                out[r * 5 + 4] = f4;
                bx[r] = make_float4(f1, cc2, cc3, f4);
            } else {
                int slot = atomicAdd(&cursor[b], 1);
                scat[slot] = (((unsigned long long)u) << 32) | (unsigned)i;
                cidx[atomicAdd(&sC, 1)] = (unsigned short)slot;
            }
        }
    }
    __syncthreads();   // cursor dead after this -> kb reuse OK
    const int C = sC;

    // ---- E: resolve collision ranks (expected ~100 elems) ----
    for (int c = tid; c < C; c += NT) {
        int slot = cidx[c];
        unsigned long long key = scat[slot];
        unsigned u = (unsigned)(key >> 32);
        int b = bucket_of(u);
        int s0 = base0[b], e0 = base0[b + 1];
        int r = s0;
        for (int q = s0; q < e0; q++) r += (scat[q] < key);

        unsigned i = (unsigned)key;
        float f0 = __uint_as_float(~u);
        float f1 = x[NPIX + i];
        float f2 = x[2 * NPIX + i];
        float f3 = x[3 * NPIX + i];
        float f4 = x[4 * NPIX + i];
        float cc2 = f0 + f2;
        float cc3 = f1 + f3;
        out[r * 5 + 0] = f0;
        out[r * 5 + 1] = f1;
        out[r * 5 + 2] = cc2;
        out[r * 5 + 3] = cc3;
        out[r * 5 + 4] = f4;
        bx[r] = make_float4(f1, cc2, cc3, f4);
    }
    __syncthreads();   // scat dead after this -> ndlist reuse OK

    // ---- F: warp 0 — greedy NMS over non-degenerate boxes only ----
    // degenerate boxes (w<=0 or h<=0) have IoU 0 with everything:
    // never suppressed, never suppress -> rows stay as written.
    if (tid < 32 && M > 0) {
        int g = 0;
        for (int base = 0; base < M; base += 32) {
            int r = base + lane;
            bool f = false;
            if (r < M) {
                float4 a = bx[r];
                f = (a.z - a.x > 0.f) && (a.w - a.y > 0.f);
            }
            unsigned bal = __ballot_sync(0xffffffffu, f);
            if (f) ndlist[g + __popc(bal & ((1u << lane) - 1u))] = r;
            g += __popc(bal);
        }
        for (int i2 = 0; i2 < g; i2++) {
            int ri = ndlist[i2];
            float4 a = bx[ri];
            float aarea = fmaxf(a.z - a.x, 0.f) * fmaxf(a.w - a.y, 0.f);
            bool sup = false;
            for (int j = lane; j < i2; j += 32) {
                if (kb[j]) {
                    float4 b2 = bx[ndlist[j]];
                    float barea = fmaxf(b2.z - b2.x, 0.f) *
                                  fmaxf(b2.w - b2.y, 0.f);
                    float iw = fminf(a.z, b2.z) - fmaxf(a.x, b2.x);
                    float ih = fminf(a.w, b2.w) - fmaxf(a.y, b2.y);
                    float inter = fmaxf(iw, 0.f) * fmaxf(ih, 0.f);
                    float uni = aarea + barea - inter;
                    if (inter / fmaxf(uni, 1e-9f) > 0.5f) sup = true;
                }
            }
            sup = __any_sync(0xffffffffu, sup);
            if (lane == 0) {
                kb[i2] = sup ? 0 : 1;
                if (sup) {   // suppressed row -> zeros (ordered after D/E
                    out[ri * 5 + 0] = 0.f;   // by the barriers above)
                    out[ri * 5 + 1] = 0.f;
                    out[ri * 5 + 2] = 0.f;
                    out[ri * 5 + 3] = 0.f;
                    out[ri * 5 + 4] = 0.f;
                }
            }
            __syncwarp();
        }
    }
}

extern "C" void kernel_launch(void* const* d_in, const int* in_sizes, int n_in,
                              void* d_out, int out_size) {
    const float* x = (const float*)d_in[0];
    float* out = (float*)d_out;
    cudaFuncSetAttribute(bb_kernel,
                         cudaFuncAttributeMaxDynamicSharedMemorySize,
                         SMEM_BYTES);
    bb_kernel<<<1, NT, SMEM_BYTES>>>(x, out);
}